// round 7
// baseline (speedup 1.0000x reference)
#include <cuda_runtime.h>
#include <cuda_bf16.h>
#include <cstdint>

#define B_   32
#define N_   2048
#define F_   1024
#define OUT_ 1024
#define HS_  8192
#define HF_  4096

// ---------------------------------------------------------------------------
// Scratch (__device__ globals; allocation-free rule). ~2.25 GB.
// ---------------------------------------------------------------------------
__device__ __align__(1024) unsigned char g_xm [268435456];   // xm fp32 -> y fp32 -> z packed
__device__ __align__(1024) unsigned char g_xs [268435456];   // xs fp32 -> z fp32
__device__ __align__(1024) unsigned char g_xsp[268435456];   // xs packed-tiled -> zt fp32
__device__ __align__(1024) unsigned char g_p  [268435456];   // argsort indices (int)
__device__ __align__(1024) unsigned char g_h  [1073741824];  // h packed-tiled -> h2 packed-tiled
__device__ __align__(1024) unsigned char g_w1 [67108864];
__device__ __align__(1024) unsigned char g_w2 [67108864];
__device__ __align__(1024) unsigned char g_w3 [16777216];
__device__ __align__(1024) unsigned char g_w4 [16777216];

// ---------------------------------------------------------------------------
// PTX helpers (plain sm_90/sm_80 ISA — no 'a'-suffix features)
// ---------------------------------------------------------------------------
__device__ __forceinline__ uint32_t smem_u32(const void* p) {
    uint32_t a;
    asm("{ .reg .u64 t; cvta.to.shared.u64 t, %1; cvt.u32.u64 %0, t; }" : "=r"(a) : "l"(p));
    return a;
}
__device__ __forceinline__ void mbar_init(uint32_t m, uint32_t cnt) {
    asm volatile("mbarrier.init.shared.b64 [%0], %1;" :: "r"(m), "r"(cnt) : "memory");
}
__device__ __forceinline__ void mbar_wait(uint32_t m, uint32_t parity) {
    uint32_t done = 0;
    while (!done) {
        asm volatile(
            "{\n\t.reg .pred p;\n\t"
            "mbarrier.try_wait.parity.acquire.cta.shared::cta.b64 p, [%1], %2, 0x989680;\n\t"
            "selp.b32 %0, 1, 0, p;\n\t}"
            : "=r"(done) : "r"(m), "r"(parity) : "memory");
    }
}
__device__ __forceinline__ void mbar_arrive(uint32_t m) {
    asm volatile("mbarrier.arrive.shared.b64 _, [%0];" :: "r"(m) : "memory");
}
__device__ __forceinline__ void mbar_expect_tx(uint32_t m, uint32_t bytes) {
    asm volatile("mbarrier.arrive.expect_tx.shared.b64 _, [%0], %1;" :: "r"(m), "r"(bytes) : "memory");
}
__device__ __forceinline__ void bulk_cp(uint32_t dst, const void* src, uint32_t bytes, uint32_t mbar) {
    asm volatile("cp.async.bulk.shared::cta.global.mbarrier::complete_tx::bytes [%0], [%1], %2, [%3];"
                 :: "r"(dst), "l"(src), "r"(bytes), "r"(mbar) : "memory");
}
__device__ __forceinline__ void ldm_x4(uint32_t* r, uint32_t addr) {
    asm volatile("ldmatrix.sync.aligned.m8n8.x4.shared.b16 {%0,%1,%2,%3}, [%4];"
                 : "=r"(r[0]), "=r"(r[1]), "=r"(r[2]), "=r"(r[3]) : "r"(addr));
}
__device__ __forceinline__ void mma_bf16(float* d, const uint32_t* a, uint32_t b0, uint32_t b1) {
    asm volatile("mma.sync.aligned.m16n8k16.row.col.f32.bf16.bf16.f32 "
                 "{%0,%1,%2,%3}, {%4,%5,%6,%7}, {%8,%9}, {%0,%1,%2,%3};"
                 : "+f"(d[0]), "+f"(d[1]), "+f"(d[2]), "+f"(d[3])
                 : "r"(a[0]), "r"(a[1]), "r"(a[2]), "r"(a[3]), "r"(b0), "r"(b1));
}

// ---------------------------------------------------------------------------
// Packed-tiled operand layout: rows grouped by 128 (tile), K by 32 (chunk).
// Tile (t, kc) = 16KB contiguous: 128 rows x 128B, row = [hi32|lo32] bf16
// groups, byte offset pre-swizzled with o ^ ((row&7)<<4).
// ---------------------------------------------------------------------------
__device__ __forceinline__ void packed_store(unsigned char* base, int NC, int r, int k,
                                             float v0, float v1) {
    size_t tb = (((size_t)(r >> 7) * NC + (k >> 5)) * 128 + (r & 127)) * 128;
    int j2 = (k & 31) * 2;
    int swz = (r & 7) << 4;
    __nv_bfloat16 h0 = __float2bfloat16(v0), h1 = __float2bfloat16(v1);
    float l0 = v0 - __bfloat162float(h0), l1 = v1 - __bfloat162float(h1);
    __nv_bfloat16 L0 = __float2bfloat16(l0), L1 = __float2bfloat16(l1);
    uint32_t hb = ((uint32_t)__bfloat16_as_ushort(h1) << 16) | __bfloat16_as_ushort(h0);
    uint32_t lb = ((uint32_t)__bfloat16_as_ushort(L1) << 16) | __bfloat16_as_ushort(L0);
    *(uint32_t*)(base + tb + (j2 ^ swz)) = hb;
    *(uint32_t*)(base + tb + ((j2 + 64) ^ swz)) = lb;
}

// ---------------------------------------------------------------------------
// transpose / sort / gather / pack
// ---------------------------------------------------------------------------
__global__ void transpose_k(const float* __restrict__ src, float* __restrict__ dst,
                            int R, int C) {
    __shared__ float tile[32][33];
    size_t bo = (size_t)blockIdx.z * R * C;
    int r0 = blockIdx.y * 32, c0 = blockIdx.x * 32;
    int tx = threadIdx.x, ty = threadIdx.y;
#pragma unroll
    for (int i = 0; i < 32; i += 8)
        tile[ty + i][tx] = src[bo + (size_t)(r0 + ty + i) * C + (c0 + tx)];
    __syncthreads();
#pragma unroll
    for (int i = 0; i < 32; i += 8)
        dst[bo + (size_t)(c0 + ty + i) * R + (r0 + tx)] = tile[tx][ty + i];
}

__global__ __launch_bounds__(512) void sort_k(const float* __restrict__ xm,
                                              float* __restrict__ xs,
                                              unsigned char* __restrict__ xsp,
                                              int* __restrict__ p) {
    __shared__ unsigned long long key[2048];
    __shared__ float val[2048];
    __shared__ int   rnk[2048];
    size_t base = (size_t)blockIdx.x * 2048;
    int tid = threadIdx.x;

    for (int i = tid; i < 2048; i += 512) {
        float v = xm[base + i];
        val[i] = v;
        unsigned u = __float_as_uint(v);
        u = (u & 0x80000000u) ? ~u : (u | 0x80000000u);
        key[i] = ((unsigned long long)u << 32) | (unsigned)i;
    }
    __syncthreads();

    for (int k2 = 2; k2 <= 2048; k2 <<= 1) {
        for (int j = k2 >> 1; j > 0; j >>= 1) {
            for (int i = tid; i < 2048; i += 512) {
                int l = i ^ j;
                if (l > i) {
                    unsigned long long a = key[i], b = key[l];
                    bool asc = ((i & k2) == 0);
                    if ((a > b) == asc) { key[i] = b; key[l] = a; }
                }
            }
            __syncthreads();
        }
    }

    for (int i = tid; i < 2048; i += 512) {
        int pi = (int)(unsigned)(key[i] & 0xffffffffu);
        p[base + i] = pi;
        rnk[pi] = i;
    }
    __syncthreads();
    int r = blockIdx.x;
    for (int i = 2 * tid; i < 2048; i += 1024) {
        float v0 = val[rnk[i]], v1 = val[rnk[i + 1]];
        xs[base + i] = v0;
        xs[base + i + 1] = v1;
        packed_store(xsp, 64, r, i, v0, v1);   // NC = 2048/32
    }
}

__global__ __launch_bounds__(512) void gather_k(const float* __restrict__ y,
                                                const int* __restrict__ p,
                                                float* __restrict__ zt) {
    size_t base = (size_t)blockIdx.x * 2048;
    for (int n = threadIdx.x; n < 2048; n += 512)
        zt[base + n] = y[base + p[base + n]];
}

__device__ __forceinline__ void pack_body(const float* __restrict__ in,
                                          unsigned char* __restrict__ out,
                                          int K, int bid, int tid) {
    size_t gid = (size_t)bid * 256 + tid;
    size_t r = gid / (unsigned)(K / 2);
    int k = (int)(gid - r * (unsigned)(K / 2)) * 2;
    const float* row = in + r * (size_t)K;
    packed_store(out, K / 32, (int)r, k, row[k], row[k + 1]);
}

__global__ __launch_bounds__(256) void pack_k(const float* __restrict__ in,
                                              unsigned char* __restrict__ out, int K) {
    pack_body(in, out, K, blockIdx.x, threadIdx.x);
}

// All four weight packs in ONE launch (keeps gemm1 at my launch index 3).
// blocks: [0,32768) w1, [32768,65536) w2, [65536,73728) w3, [73728,81920) w4
__global__ __launch_bounds__(256) void packW_k(const float* __restrict__ sw1, unsigned char* __restrict__ o1,
                                               const float* __restrict__ sw2, unsigned char* __restrict__ o2,
                                               const float* __restrict__ fw1, unsigned char* __restrict__ o3,
                                               const float* __restrict__ fw2, unsigned char* __restrict__ o4) {
    int b = blockIdx.x, t = threadIdx.x;
    if (b < 32768)       pack_body(sw1, o1, N_,  b,         t);
    else if (b < 65536)  pack_body(sw2, o2, HS_, b - 32768, t);
    else if (b < 73728)  pack_body(fw1, o3, F_,  b - 65536, t);
    else                 pack_body(fw2, o4, HF_, b - 73728, t);
}

// ---------------------------------------------------------------------------
// bf16x3 mma.sync GEMM. CTA tile 256(M) x 128(N).
// 288 threads: warps 0-7 compute (warp tile 64x64), warp 8 = producer.
// 3-stage cp.async.bulk pipeline (48KB/stage).
// MODE 0: bias+relu -> packed-tiled. MODE 1: bias+skip fp32. MODE 2: bias fp32.
// ---------------------------------------------------------------------------
#define S_ 3
#define STAGE_B 49152
#define GEMM_SMEM (1024 + S_ * STAGE_B)

template <int MODE>
__global__ __launch_bounds__(288, 1) void gemm_mma(
    const unsigned char* __restrict__ Ap, const unsigned char* __restrict__ Bp,
    const float* __restrict__ bias, const float* __restrict__ Skip,
    float* __restrict__ Cf, unsigned char* __restrict__ Cp,
    int M, int Ntot, int K) {
    extern __shared__ __align__(1024) unsigned char smem_raw[];
    const uint32_t sb = smem_u32(smem_raw);
    const int tid = threadIdx.x;
    const int NC = K / 32;

    const uint32_t FULL0 = sb;            // full[s] at sb+16s, free[s] at sb+16s+8
    const uint32_t DATA  = sb + 1024;

    if (tid == 0) {
        for (int s = 0; s < S_; s++) {
            mbar_init(FULL0 + 16 * s, 1);     // full: expect_tx arrive + bytes
            mbar_init(FULL0 + 16 * s + 8, 256); // free: 256 compute threads
        }
        asm volatile("fence.proxy.async.shared::cta;" ::: "memory");
    }
    __syncthreads();

    const unsigned char* At0 = Ap + (size_t)(2 * blockIdx.y)     * NC * 16384;
    const unsigned char* At1 = Ap + (size_t)(2 * blockIdx.y + 1) * NC * 16384;
    const unsigned char* Bt  = Bp + (size_t)blockIdx.x           * NC * 16384;

    // ---------------- producer warp (warp 8) ----------------
    if (tid >= 256) {
        if (tid == 256) {
            for (int kp = 0; kp < NC; kp++) {
                int sp = kp % S_;
                if (kp >= S_) mbar_wait(FULL0 + 16 * sp + 8, ((kp / S_) - 1) & 1);
                uint32_t st = DATA + (uint32_t)sp * STAGE_B;
                mbar_expect_tx(FULL0 + 16 * sp, STAGE_B);
                bulk_cp(st,          At0 + (size_t)kp * 16384, 16384u, FULL0 + 16 * sp);
                bulk_cp(st + 16384u, At1 + (size_t)kp * 16384, 16384u, FULL0 + 16 * sp);
                bulk_cp(st + 32768u, Bt  + (size_t)kp * 16384, 16384u, FULL0 + 16 * sp);
            }
        }
        return;
    }

    // ---------------- compute warps (0-7) ----------------
    const int lane = tid & 31, wid = tid >> 5;
    const int wm = wid & 3, wn = wid >> 2;         // 4 x 2 warp grid (M x N)
    const int m0 = blockIdx.y * 256, n0 = blockIdx.x * 128;

    float acc[4][8][4];
#pragma unroll
    for (int a = 0; a < 4; a++)
#pragma unroll
        for (int b = 0; b < 8; b++)
#pragma unroll
            for (int c = 0; c < 4; c++) acc[a][b][c] = 0.f;

    const int lr = lane & 15;
    const int lh = (lane >> 4) << 4;

    for (int kc = 0; kc < NC; kc++) {
        const int s = kc % S_;
        mbar_wait(FULL0 + 16 * s, (kc / S_) & 1);

        const uint32_t Ab = DATA + (uint32_t)s * STAGE_B;
        const uint32_t Bb = Ab + 32768u;

#pragma unroll
        for (int ks = 0; ks < 2; ks++) {
            uint32_t a[4][4], b1[4][4], b2[4][4];
            // Ah
#pragma unroll
            for (int mt = 0; mt < 4; mt++) {
                int row = wm * 64 + mt * 16 + lr;
                ldm_x4(a[mt], Ab + row * 128 + ((ks * 32 + lh) ^ ((row & 7) << 4)));
            }
            // Bh
#pragma unroll
            for (int nq = 0; nq < 4; nq++) {
                int row = wn * 64 + nq * 16 + lr;
                ldm_x4(b1[nq], Bb + row * 128 + ((ks * 32 + lh) ^ ((row & 7) << 4)));
            }
            // pass 1: Ah * Bh
#pragma unroll
            for (int mt = 0; mt < 4; mt++)
#pragma unroll
                for (int nq = 0; nq < 4; nq++) {
                    mma_bf16(acc[mt][2 * nq],     a[mt], b1[nq][0], b1[nq][2]);
                    mma_bf16(acc[mt][2 * nq + 1], a[mt], b1[nq][1], b1[nq][3]);
                }
            // Bl
#pragma unroll
            for (int nq = 0; nq < 4; nq++) {
                int row = wn * 64 + nq * 16 + lr;
                ldm_x4(b2[nq], Bb + row * 128 + ((64 + ks * 32 + lh) ^ ((row & 7) << 4)));
            }
            // pass 2: Ah * Bl
#pragma unroll
            for (int mt = 0; mt < 4; mt++)
#pragma unroll
                for (int nq = 0; nq < 4; nq++) {
                    mma_bf16(acc[mt][2 * nq],     a[mt], b2[nq][0], b2[nq][2]);
                    mma_bf16(acc[mt][2 * nq + 1], a[mt], b2[nq][1], b2[nq][3]);
                }
            // Al (overwrite Ah)
#pragma unroll
            for (int mt = 0; mt < 4; mt++) {
                int row = wm * 64 + mt * 16 + lr;
                ldm_x4(a[mt], Ab + row * 128 + ((64 + ks * 32 + lh) ^ ((row & 7) << 4)));
            }
            // pass 3: Al * Bh
#pragma unroll
            for (int mt = 0; mt < 4; mt++)
#pragma unroll
                for (int nq = 0; nq < 4; nq++) {
                    mma_bf16(acc[mt][2 * nq],     a[mt], b1[nq][0], b1[nq][2]);
                    mma_bf16(acc[mt][2 * nq + 1], a[mt], b1[nq][1], b1[nq][3]);
                }
        }
        mbar_arrive(FULL0 + 16 * s + 8);
    }

    // ---- epilogue ----
    const int NCo = Ntot / 32;
#pragma unroll
    for (int mt = 0; mt < 4; mt++) {
        int r0 = m0 + wm * 64 + mt * 16 + (lane >> 2);
#pragma unroll
        for (int nf = 0; nf < 8; nf++) {
            int c = n0 + wn * 64 + nf * 8 + (lane & 3) * 2;
            float b0 = bias[c], b1v = bias[c + 1];
            float v00 = acc[mt][nf][0] + b0, v01 = acc[mt][nf][1] + b1v;
            float v10 = acc[mt][nf][2] + b0, v11 = acc[mt][nf][3] + b1v;
            int r1 = r0 + 8;
            if (MODE == 0) {
                packed_store(Cp, NCo, r0, c, fmaxf(v00, 0.f), fmaxf(v01, 0.f));
                packed_store(Cp, NCo, r1, c, fmaxf(v10, 0.f), fmaxf(v11, 0.f));
            } else if (MODE == 1) {
                const float2 s0 = *(const float2*)(Skip + (size_t)r0 * Ntot + c);
                const float2 s1 = *(const float2*)(Skip + (size_t)r1 * Ntot + c);
                *(float2*)(Cf + (size_t)r0 * Ntot + c) = make_float2(v00 + s0.x, v01 + s0.y);
                *(float2*)(Cf + (size_t)r1 * Ntot + c) = make_float2(v10 + s1.x, v11 + s1.y);
            } else {
                *(float2*)(Cf + (size_t)r0 * Ntot + c) = make_float2(v00, v01);
                *(float2*)(Cf + (size_t)r1 * Ntot + c) = make_float2(v10, v11);
            }
        }
    }
}

// ---------------------------------------------------------------------------
extern "C" void kernel_launch(void* const* d_in, const int* in_sizes, int n_in,
                              void* d_out, int out_size) {
    const float* x   = (const float*)d_in[0];
    const float* sw1 = (const float*)d_in[1];
    const float* sb1 = (const float*)d_in[2];
    const float* sw2 = (const float*)d_in[3];
    const float* sb2 = (const float*)d_in[4];
    const float* fw1 = (const float*)d_in[5];
    const float* fb1 = (const float*)d_in[6];
    const float* fw2 = (const float*)d_in[7];
    const float* fb2 = (const float*)d_in[8];
    float* out = (float*)d_out;

    unsigned char *xm, *xs, *xsp, *p, *h, *w1, *w2, *w3, *w4;
    cudaGetSymbolAddress((void**)&xm,  g_xm);
    cudaGetSymbolAddress((void**)&xs,  g_xs);
    cudaGetSymbolAddress((void**)&xsp, g_xsp);
    cudaGetSymbolAddress((void**)&p,   g_p);
    cudaGetSymbolAddress((void**)&h,   g_h);
    cudaGetSymbolAddress((void**)&w1,  g_w1);
    cudaGetSymbolAddress((void**)&w2,  g_w2);
    cudaGetSymbolAddress((void**)&w3,  g_w3);
    cudaGetSymbolAddress((void**)&w4,  g_w4);

    cudaFuncSetAttribute((const void*)gemm_mma<0>, cudaFuncAttributeMaxDynamicSharedMemorySize, GEMM_SMEM);
    cudaFuncSetAttribute((const void*)gemm_mma<1>, cudaFuncAttributeMaxDynamicSharedMemorySize, GEMM_SMEM);
    cudaFuncSetAttribute((const void*)gemm_mma<2>, cudaFuncAttributeMaxDynamicSharedMemorySize, GEMM_SMEM);

    const int M1 = B_ * F_;   // 32768
    const int M2 = B_ * N_;   // 65536

    // my launch index (ncu -s 5 with 2 hidden harness launches => profiles idx 3):
    transpose_k<<<dim3(F_ / 32, N_ / 32, B_), dim3(32, 8)>>>(x, (float*)xm, N_, F_);    // 0
    sort_k<<<M1, 512>>>((const float*)xm, (float*)xs, xsp, (int*)p);                    // 1
    packW_k<<<81920, 256>>>(sw1, w1, sw2, w2, fw1, w3, fw2, w4);                        // 2

    // 3) h = relu(xs @ sw1^T + sb1) -> packed-tiled    <== ncu target
    gemm_mma<0><<<dim3(HS_ / 128, M1 / 256), 288, GEMM_SMEM>>>(                         // 3
        xsp, w1, sb1, nullptr, nullptr, h, M1, HS_, N_);

    // 4) y = h @ sw2^T + sb2 + xs -> fp32 (into xm)
    gemm_mma<1><<<dim3(N_ / 128, M1 / 256), 288, GEMM_SMEM>>>(
        h, w2, sb2, (const float*)xs, (float*)xm, nullptr, M1, N_, HS_);

    // 5) zt = gather(y, p) (into xsp as fp32)
    gather_k<<<M1, 512>>>((const float*)xm, (const int*)p, (float*)xsp);

    // 6) z[b,n,f] = zt[b,f,n] (into xs)
    transpose_k<<<dim3(N_ / 32, F_ / 32, B_), dim3(32, 8)>>>((const float*)xsp, (float*)xs, F_, N_);

    // 6b) pack z -> tiled (into xm)
    pack_k<<<(int)((size_t)M2 * F_ / 512), 256>>>((const float*)xs, xm, F_);

    // 7) h2 = relu(z @ fw1^T + fb1) -> packed-tiled (into h)
    gemm_mma<0><<<dim3(HF_ / 128, M2 / 256), 288, GEMM_SMEM>>>(
        xm, w3, fb1, nullptr, nullptr, h, M2, HF_, F_);

    // 8) out = h2 @ fw2^T + fb2 -> fp32
    gemm_mma<2><<<dim3(OUT_ / 128, M2 / 256), 288, GEMM_SMEM>>>(
        h, w4, fb2, nullptr, out, nullptr, M2, OUT_, HF_);
}

// round 8
// speedup vs baseline: 1.1388x; 1.1388x over previous
#include <cuda_runtime.h>
#include <cuda_bf16.h>
#include <cstdint>

#define B_   32
#define N_   2048
#define F_   1024
#define OUT_ 1024
#define HS_  8192
#define HF_  4096

// ---------------------------------------------------------------------------
// Scratch (__device__ globals; allocation-free rule). ~2.25 GB.
// ---------------------------------------------------------------------------
__device__ __align__(1024) unsigned char g_xm [268435456];   // xm fp32 -> y fp32 -> z packed
__device__ __align__(1024) unsigned char g_xs [268435456];   // xs fp32 -> z fp32
__device__ __align__(1024) unsigned char g_xsp[268435456];   // xs packed-tiled -> zt fp32
__device__ __align__(1024) unsigned char g_p  [268435456];   // argsort indices (int)
__device__ __align__(1024) unsigned char g_h  [1073741824];  // h packed-tiled -> h2 packed-tiled
__device__ __align__(1024) unsigned char g_w1 [67108864];
__device__ __align__(1024) unsigned char g_w2 [67108864];
__device__ __align__(1024) unsigned char g_w3 [16777216];
__device__ __align__(1024) unsigned char g_w4 [16777216];

// ---------------------------------------------------------------------------
// PTX helpers (plain sm_90/sm_80 ISA — no 'a'-suffix features)
// ---------------------------------------------------------------------------
__device__ __forceinline__ uint32_t smem_u32(const void* p) {
    uint32_t a;
    asm("{ .reg .u64 t; cvta.to.shared.u64 t, %1; cvt.u32.u64 %0, t; }" : "=r"(a) : "l"(p));
    return a;
}
__device__ __forceinline__ void mbar_init(uint32_t m, uint32_t cnt) {
    asm volatile("mbarrier.init.shared.b64 [%0], %1;" :: "r"(m), "r"(cnt) : "memory");
}
__device__ __forceinline__ void mbar_wait(uint32_t m, uint32_t parity) {
    uint32_t done = 0;
    while (!done) {
        asm volatile(
            "{\n\t.reg .pred p;\n\t"
            "mbarrier.try_wait.parity.acquire.cta.shared::cta.b64 p, [%1], %2, 0x989680;\n\t"
            "selp.b32 %0, 1, 0, p;\n\t}"
            : "=r"(done) : "r"(m), "r"(parity) : "memory");
    }
}
__device__ __forceinline__ void mbar_arrive(uint32_t m) {
    asm volatile("mbarrier.arrive.shared.b64 _, [%0];" :: "r"(m) : "memory");
}
__device__ __forceinline__ void mbar_expect_tx(uint32_t m, uint32_t bytes) {
    asm volatile("mbarrier.arrive.expect_tx.shared.b64 _, [%0], %1;" :: "r"(m), "r"(bytes) : "memory");
}
__device__ __forceinline__ void bulk_cp(uint32_t dst, const void* src, uint32_t bytes, uint32_t mbar) {
    asm volatile("cp.async.bulk.shared::cta.global.mbarrier::complete_tx::bytes [%0], [%1], %2, [%3];"
                 :: "r"(dst), "l"(src), "r"(bytes), "r"(mbar) : "memory");
}
__device__ __forceinline__ void ldm_x4(uint32_t* r, uint32_t addr) {
    asm volatile("ldmatrix.sync.aligned.m8n8.x4.shared.b16 {%0,%1,%2,%3}, [%4];"
                 : "=r"(r[0]), "=r"(r[1]), "=r"(r[2]), "=r"(r[3]) : "r"(addr));
}
__device__ __forceinline__ void mma_bf16(float* d, const uint32_t* a, uint32_t b0, uint32_t b1) {
    asm volatile("mma.sync.aligned.m16n8k16.row.col.f32.bf16.bf16.f32 "
                 "{%0,%1,%2,%3}, {%4,%5,%6,%7}, {%8,%9}, {%0,%1,%2,%3};"
                 : "+f"(d[0]), "+f"(d[1]), "+f"(d[2]), "+f"(d[3])
                 : "r"(a[0]), "r"(a[1]), "r"(a[2]), "r"(a[3]), "r"(b0), "r"(b1));
}

// ---------------------------------------------------------------------------
// Packed-tiled operand layout: rows grouped by 128 (tile), K by 32 (chunk).
// Tile (t, kc) = 16KB contiguous: 128 rows x 128B, row = [hi32|lo32] bf16
// groups, byte offset pre-swizzled with o ^ ((row&7)<<4).
// ---------------------------------------------------------------------------
__device__ __forceinline__ void packed_store(unsigned char* base, int NC, int r, int k,
                                             float v0, float v1) {
    size_t tb = (((size_t)(r >> 7) * NC + (k >> 5)) * 128 + (r & 127)) * 128;
    int j2 = (k & 31) * 2;
    int swz = (r & 7) << 4;
    __nv_bfloat16 h0 = __float2bfloat16(v0), h1 = __float2bfloat16(v1);
    float l0 = v0 - __bfloat162float(h0), l1 = v1 - __bfloat162float(h1);
    __nv_bfloat16 L0 = __float2bfloat16(l0), L1 = __float2bfloat16(l1);
    uint32_t hb = ((uint32_t)__bfloat16_as_ushort(h1) << 16) | __bfloat16_as_ushort(h0);
    uint32_t lb = ((uint32_t)__bfloat16_as_ushort(L1) << 16) | __bfloat16_as_ushort(L0);
    *(uint32_t*)(base + tb + (j2 ^ swz)) = hb;
    *(uint32_t*)(base + tb + ((j2 + 64) ^ swz)) = lb;
}

// ---------------------------------------------------------------------------
// transpose / sort / gather / pack
// ---------------------------------------------------------------------------
__global__ void transpose_k(const float* __restrict__ src, float* __restrict__ dst,
                            int R, int C) {
    __shared__ float tile[32][33];
    size_t bo = (size_t)blockIdx.z * R * C;
    int r0 = blockIdx.y * 32, c0 = blockIdx.x * 32;
    int tx = threadIdx.x, ty = threadIdx.y;
#pragma unroll
    for (int i = 0; i < 32; i += 8)
        tile[ty + i][tx] = src[bo + (size_t)(r0 + ty + i) * C + (c0 + tx)];
    __syncthreads();
#pragma unroll
    for (int i = 0; i < 32; i += 8)
        dst[bo + (size_t)(c0 + ty + i) * R + (r0 + tx)] = tile[tx][ty + i];
}

__global__ __launch_bounds__(512) void sort_k(const float* __restrict__ xm,
                                              float* __restrict__ xs,
                                              unsigned char* __restrict__ xsp,
                                              int* __restrict__ p) {
    __shared__ unsigned long long key[2048];
    __shared__ float val[2048];
    __shared__ int   rnk[2048];
    size_t base = (size_t)blockIdx.x * 2048;
    int tid = threadIdx.x;

    for (int i = tid; i < 2048; i += 512) {
        float v = xm[base + i];
        val[i] = v;
        unsigned u = __float_as_uint(v);
        u = (u & 0x80000000u) ? ~u : (u | 0x80000000u);
        key[i] = ((unsigned long long)u << 32) | (unsigned)i;
    }
    __syncthreads();

    for (int k2 = 2; k2 <= 2048; k2 <<= 1) {
        for (int j = k2 >> 1; j > 0; j >>= 1) {
            for (int i = tid; i < 2048; i += 512) {
                int l = i ^ j;
                if (l > i) {
                    unsigned long long a = key[i], b = key[l];
                    bool asc = ((i & k2) == 0);
                    if ((a > b) == asc) { key[i] = b; key[l] = a; }
                }
            }
            __syncthreads();
        }
    }

    for (int i = tid; i < 2048; i += 512) {
        int pi = (int)(unsigned)(key[i] & 0xffffffffu);
        p[base + i] = pi;
        rnk[pi] = i;
    }
    __syncthreads();
    int r = blockIdx.x;
    for (int i = 2 * tid; i < 2048; i += 1024) {
        float v0 = val[rnk[i]], v1 = val[rnk[i + 1]];
        xs[base + i] = v0;
        xs[base + i + 1] = v1;
        packed_store(xsp, 64, r, i, v0, v1);   // NC = 2048/32
    }
}

__global__ __launch_bounds__(512) void gather_k(const float* __restrict__ y,
                                                const int* __restrict__ p,
                                                float* __restrict__ zt) {
    size_t base = (size_t)blockIdx.x * 2048;
    for (int n = threadIdx.x; n < 2048; n += 512)
        zt[base + n] = y[base + p[base + n]];
}

__device__ __forceinline__ void pack_body(const float* __restrict__ in,
                                          unsigned char* __restrict__ out,
                                          int K, int bid, int tid) {
    size_t gid = (size_t)bid * 256 + tid;
    size_t r = gid / (unsigned)(K / 2);
    int k = (int)(gid - r * (unsigned)(K / 2)) * 2;
    const float* row = in + r * (size_t)K;
    packed_store(out, K / 32, (int)r, k, row[k], row[k + 1]);
}

__global__ __launch_bounds__(256) void pack_k(const float* __restrict__ in,
                                              unsigned char* __restrict__ out, int K) {
    pack_body(in, out, K, blockIdx.x, threadIdx.x);
}

// All four weight packs in ONE launch (keeps gemm1 at my launch index 3).
__global__ __launch_bounds__(256) void packW_k(const float* __restrict__ sw1, unsigned char* __restrict__ o1,
                                               const float* __restrict__ sw2, unsigned char* __restrict__ o2,
                                               const float* __restrict__ fw1, unsigned char* __restrict__ o3,
                                               const float* __restrict__ fw2, unsigned char* __restrict__ o4) {
    int b = blockIdx.x, t = threadIdx.x;
    if (b < 32768)       pack_body(sw1, o1, N_,  b,         t);
    else if (b < 65536)  pack_body(sw2, o2, HS_, b - 32768, t);
    else if (b < 73728)  pack_body(fw1, o3, F_,  b - 65536, t);
    else                 pack_body(fw2, o4, HF_, b - 73728, t);
}

// ---------------------------------------------------------------------------
// bf16x3 mma.sync GEMM. CTA tile 128x128, 256 thr, warp tile 32x64.
// 3-stage cp.async.bulk pipeline (32KB/stage), 2 CTAs/SM for overlap.
// MODE 0: bias+relu -> packed-tiled. MODE 1: bias+skip fp32. MODE 2: bias fp32.
// ---------------------------------------------------------------------------
#define S_ 3
#define STAGE_B 32768
#define GEMM_SMEM (1024 + S_ * STAGE_B)

template <int MODE>
__global__ __launch_bounds__(256, 2) void gemm_mma(
    const unsigned char* __restrict__ Ap, const unsigned char* __restrict__ Bp,
    const float* __restrict__ bias, const float* __restrict__ Skip,
    float* __restrict__ Cf, unsigned char* __restrict__ Cp,
    int M, int Ntot, int K) {
    extern __shared__ __align__(1024) unsigned char smem_raw[];
    const uint32_t sb = smem_u32(smem_raw);
    const int tid = threadIdx.x;
    const int lane = tid & 31, wid = tid >> 5;
    const int wm = wid & 3, wn = wid >> 2;         // 4 x 2 warp grid (M x N)
    const int NC = K / 32;
    const int m0 = blockIdx.y * 128, n0 = blockIdx.x * 128;

    const uint32_t FULL0 = sb;            // full[s] at sb+16s, free[s] at sb+16s+8
    const uint32_t DATA  = sb + 1024;

    if (tid == 0) {
        for (int s = 0; s < S_; s++) {
            mbar_init(FULL0 + 16 * s, 1);
            mbar_init(FULL0 + 16 * s + 8, 256);
        }
        asm volatile("fence.proxy.async.shared::cta;" ::: "memory");
    }
    __syncthreads();

    const unsigned char* Atile = Ap + (size_t)blockIdx.y * NC * 16384;
    const unsigned char* Btile = Bp + (size_t)blockIdx.x * NC * 16384;

    if (tid == 0) {
#pragma unroll
        for (int s = 0; s < S_ - 1; s++) {
            uint32_t st = DATA + (uint32_t)s * STAGE_B;
            mbar_expect_tx(FULL0 + 16 * s, STAGE_B);
            bulk_cp(st,          Atile + (size_t)s * 16384, 16384u, FULL0 + 16 * s);
            bulk_cp(st + 16384u, Btile + (size_t)s * 16384, 16384u, FULL0 + 16 * s);
        }
    }

    float acc[2][8][4];
#pragma unroll
    for (int a = 0; a < 2; a++)
#pragma unroll
        for (int b = 0; b < 8; b++)
#pragma unroll
            for (int c = 0; c < 4; c++) acc[a][b][c] = 0.f;

    const int lr = lane & 15;
    const int lh = (lane >> 4) << 4;

    for (int kc = 0; kc < NC; kc++) {
        const int s = kc % S_;
        if (tid == 0) {
            int kp = kc + S_ - 1;
            if (kp < NC) {
                int sp = kp % S_;
                if (kp >= S_) mbar_wait(FULL0 + 16 * sp + 8, ((kp / S_) - 1) & 1);
                uint32_t st = DATA + (uint32_t)sp * STAGE_B;
                mbar_expect_tx(FULL0 + 16 * sp, STAGE_B);
                bulk_cp(st,          Atile + (size_t)kp * 16384, 16384u, FULL0 + 16 * sp);
                bulk_cp(st + 16384u, Btile + (size_t)kp * 16384, 16384u, FULL0 + 16 * sp);
            }
        }
        mbar_wait(FULL0 + 16 * s, (kc / S_) & 1);

        const uint32_t Ab = DATA + (uint32_t)s * STAGE_B;
        const uint32_t Bb = Ab + 16384u;

        uint32_t a[2][2][4];   // [ks][mt] : Ah then overwritten by Al
        uint32_t bh[2][4][4];  // [ks][nq] : Bh cached across passes 1 & 3
#pragma unroll
        for (int ks = 0; ks < 2; ks++)
#pragma unroll
            for (int mt = 0; mt < 2; mt++) {
                int row = wm * 32 + mt * 16 + lr;
                ldm_x4(a[ks][mt], Ab + row * 128 + ((ks * 32 + lh) ^ ((row & 7) << 4)));
            }
#pragma unroll
        for (int ks = 0; ks < 2; ks++)
#pragma unroll
            for (int nq = 0; nq < 4; nq++) {
                int row = wn * 64 + nq * 16 + lr;
                ldm_x4(bh[ks][nq], Bb + row * 128 + ((ks * 32 + lh) ^ ((row & 7) << 4)));
            }
        // pass 1: Ah * Bh
#pragma unroll
        for (int ks = 0; ks < 2; ks++)
#pragma unroll
            for (int mt = 0; mt < 2; mt++)
#pragma unroll
                for (int nq = 0; nq < 4; nq++) {
                    mma_bf16(acc[mt][2 * nq],     a[ks][mt], bh[ks][nq][0], bh[ks][nq][2]);
                    mma_bf16(acc[mt][2 * nq + 1], a[ks][mt], bh[ks][nq][1], bh[ks][nq][3]);
                }
        // pass 2: Ah * Bl
#pragma unroll
        for (int ks = 0; ks < 2; ks++) {
            uint32_t bl[4][4];
#pragma unroll
            for (int nq = 0; nq < 4; nq++) {
                int row = wn * 64 + nq * 16 + lr;
                ldm_x4(bl[nq], Bb + row * 128 + ((64 + ks * 32 + lh) ^ ((row & 7) << 4)));
            }
#pragma unroll
            for (int mt = 0; mt < 2; mt++)
#pragma unroll
                for (int nq = 0; nq < 4; nq++) {
                    mma_bf16(acc[mt][2 * nq],     a[ks][mt], bl[nq][0], bl[nq][2]);
                    mma_bf16(acc[mt][2 * nq + 1], a[ks][mt], bl[nq][1], bl[nq][3]);
                }
        }
        // pass 3: Al * Bh
#pragma unroll
        for (int ks = 0; ks < 2; ks++)
#pragma unroll
            for (int mt = 0; mt < 2; mt++) {
                int row = wm * 32 + mt * 16 + lr;
                ldm_x4(a[ks][mt], Ab + row * 128 + ((64 + ks * 32 + lh) ^ ((row & 7) << 4)));
            }
#pragma unroll
        for (int ks = 0; ks < 2; ks++)
#pragma unroll
            for (int mt = 0; mt < 2; mt++)
#pragma unroll
                for (int nq = 0; nq < 4; nq++) {
                    mma_bf16(acc[mt][2 * nq],     a[ks][mt], bh[ks][nq][0], bh[ks][nq][2]);
                    mma_bf16(acc[mt][2 * nq + 1], a[ks][mt], bh[ks][nq][1], bh[ks][nq][3]);
                }
        mbar_arrive(FULL0 + 16 * s + 8);
    }

    // ---- epilogue ----
    const int NCo = Ntot / 32;
#pragma unroll
    for (int mt = 0; mt < 2; mt++) {
        int r0 = m0 + wm * 32 + mt * 16 + (lane >> 2);
#pragma unroll
        for (int nf = 0; nf < 8; nf++) {
            int c = n0 + wn * 64 + nf * 8 + (lane & 3) * 2;
            float b0 = bias[c], b1v = bias[c + 1];
            float v00 = acc[mt][nf][0] + b0, v01 = acc[mt][nf][1] + b1v;
            float v10 = acc[mt][nf][2] + b0, v11 = acc[mt][nf][3] + b1v;
            int r1 = r0 + 8;
            if (MODE == 0) {
                packed_store(Cp, NCo, r0, c, fmaxf(v00, 0.f), fmaxf(v01, 0.f));
                packed_store(Cp, NCo, r1, c, fmaxf(v10, 0.f), fmaxf(v11, 0.f));
            } else if (MODE == 1) {
                const float2 s0 = *(const float2*)(Skip + (size_t)r0 * Ntot + c);
                const float2 s1 = *(const float2*)(Skip + (size_t)r1 * Ntot + c);
                *(float2*)(Cf + (size_t)r0 * Ntot + c) = make_float2(v00 + s0.x, v01 + s0.y);
                *(float2*)(Cf + (size_t)r1 * Ntot + c) = make_float2(v10 + s1.x, v11 + s1.y);
            } else {
                *(float2*)(Cf + (size_t)r0 * Ntot + c) = make_float2(v00, v01);
                *(float2*)(Cf + (size_t)r1 * Ntot + c) = make_float2(v10, v11);
            }
        }
    }
}

// ---------------------------------------------------------------------------
extern "C" void kernel_launch(void* const* d_in, const int* in_sizes, int n_in,
                              void* d_out, int out_size) {
    const float* x   = (const float*)d_in[0];
    const float* sw1 = (const float*)d_in[1];
    const float* sb1 = (const float*)d_in[2];
    const float* sw2 = (const float*)d_in[3];
    const float* sb2 = (const float*)d_in[4];
    const float* fw1 = (const float*)d_in[5];
    const float* fb1 = (const float*)d_in[6];
    const float* fw2 = (const float*)d_in[7];
    const float* fb2 = (const float*)d_in[8];
    float* out = (float*)d_out;

    unsigned char *xm, *xs, *xsp, *p, *h, *w1, *w2, *w3, *w4;
    cudaGetSymbolAddress((void**)&xm,  g_xm);
    cudaGetSymbolAddress((void**)&xs,  g_xs);
    cudaGetSymbolAddress((void**)&xsp, g_xsp);
    cudaGetSymbolAddress((void**)&p,   g_p);
    cudaGetSymbolAddress((void**)&h,   g_h);
    cudaGetSymbolAddress((void**)&w1,  g_w1);
    cudaGetSymbolAddress((void**)&w2,  g_w2);
    cudaGetSymbolAddress((void**)&w3,  g_w3);
    cudaGetSymbolAddress((void**)&w4,  g_w4);

    cudaFuncSetAttribute((const void*)gemm_mma<0>, cudaFuncAttributeMaxDynamicSharedMemorySize, GEMM_SMEM);
    cudaFuncSetAttribute((const void*)gemm_mma<1>, cudaFuncAttributeMaxDynamicSharedMemorySize, GEMM_SMEM);
    cudaFuncSetAttribute((const void*)gemm_mma<2>, cudaFuncAttributeMaxDynamicSharedMemorySize, GEMM_SMEM);

    const int M1 = B_ * F_;   // 32768
    const int M2 = B_ * N_;   // 65536

    // launch order keeps gemm1 at my index 3 (ncu -s 5 lands there with 2 hidden launches)
    transpose_k<<<dim3(F_ / 32, N_ / 32, B_), dim3(32, 8)>>>(x, (float*)xm, N_, F_);    // 0
    sort_k<<<M1, 512>>>((const float*)xm, (float*)xs, xsp, (int*)p);                    // 1
    packW_k<<<81920, 256>>>(sw1, w1, sw2, w2, fw1, w3, fw2, w4);                        // 2

    // 3) h = relu(xs @ sw1^T + sb1) -> packed-tiled    <== ncu target
    gemm_mma<0><<<dim3(HS_ / 128, M1 / 128), 256, GEMM_SMEM>>>(                         // 3
        xsp, w1, sb1, nullptr, nullptr, h, M1, HS_, N_);

    // 4) y = h @ sw2^T + sb2 + xs -> fp32 (into xm)
    gemm_mma<1><<<dim3(N_ / 128, M1 / 128), 256, GEMM_SMEM>>>(
        h, w2, sb2, (const float*)xs, (float*)xm, nullptr, M1, N_, HS_);

    // 5) zt = gather(y, p) (into xsp as fp32)
    gather_k<<<M1, 512>>>((const float*)xm, (const int*)p, (float*)xsp);

    // 6) z[b,n,f] = zt[b,f,n] (into xs)
    transpose_k<<<dim3(N_ / 32, F_ / 32, B_), dim3(32, 8)>>>((const float*)xsp, (float*)xs, F_, N_);

    // 6b) pack z -> tiled (into xm)
    pack_k<<<(int)((size_t)M2 * F_ / 512), 256>>>((const float*)xs, xm, F_);

    // 7) h2 = relu(z @ fw1^T + fb1) -> packed-tiled (into h)
    gemm_mma<0><<<dim3(HF_ / 128, M2 / 128), 256, GEMM_SMEM>>>(
        xm, w3, fb1, nullptr, nullptr, h, M2, HF_, F_);

    // 8) out = h2 @ fw2^T + fb2 -> fp32
    gemm_mma<2><<<dim3(OUT_ / 128, M2 / 128), 256, GEMM_SMEM>>>(
        h, w4, fb2, nullptr, out, nullptr, M2, OUT_, HF_);
}

// round 9
// speedup vs baseline: 1.1422x; 1.0030x over previous
#include <cuda_runtime.h>
#include <cuda_bf16.h>
#include <cstdint>

#define B_   32
#define N_   2048
#define F_   1024
#define OUT_ 1024
#define HS_  8192
#define HF_  4096

// ---------------------------------------------------------------------------
// Scratch (__device__ globals; allocation-free rule). ~2.25 GB.
// ---------------------------------------------------------------------------
__device__ __align__(1024) unsigned char g_xm [268435456];   // xm fp32 -> y fp32 -> z packed
__device__ __align__(1024) unsigned char g_xs [268435456];   // xs fp32 -> z fp32
__device__ __align__(1024) unsigned char g_xsp[268435456];   // xs packed-tiled -> zt fp32
__device__ __align__(1024) unsigned char g_p  [268435456];   // argsort indices (int)
__device__ __align__(1024) unsigned char g_h  [1073741824];  // h packed-tiled -> h2 packed-tiled
__device__ __align__(1024) unsigned char g_w1 [67108864];
__device__ __align__(1024) unsigned char g_w2 [67108864];
__device__ __align__(1024) unsigned char g_w3 [16777216];
__device__ __align__(1024) unsigned char g_w4 [16777216];

// ---------------------------------------------------------------------------
// PTX helpers (plain sm_90/sm_80 ISA — no 'a'-suffix features)
// ---------------------------------------------------------------------------
__device__ __forceinline__ uint32_t smem_u32(const void* p) {
    uint32_t a;
    asm("{ .reg .u64 t; cvta.to.shared.u64 t, %1; cvt.u32.u64 %0, t; }" : "=r"(a) : "l"(p));
    return a;
}
__device__ __forceinline__ void mbar_init(uint32_t m, uint32_t cnt) {
    asm volatile("mbarrier.init.shared.b64 [%0], %1;" :: "r"(m), "r"(cnt) : "memory");
}
__device__ __forceinline__ void mbar_wait(uint32_t m, uint32_t parity) {
    uint32_t done = 0;
    while (!done) {
        asm volatile(
            "{\n\t.reg .pred p;\n\t"
            "mbarrier.try_wait.parity.acquire.cta.shared::cta.b64 p, [%1], %2, 0x989680;\n\t"
            "selp.b32 %0, 1, 0, p;\n\t}"
            : "=r"(done) : "r"(m), "r"(parity) : "memory");
    }
}
__device__ __forceinline__ void mbar_arrive(uint32_t m) {
    asm volatile("mbarrier.arrive.shared.b64 _, [%0];" :: "r"(m) : "memory");
}
__device__ __forceinline__ void mbar_expect_tx(uint32_t m, uint32_t bytes) {
    asm volatile("mbarrier.arrive.expect_tx.shared.b64 _, [%0], %1;" :: "r"(m), "r"(bytes) : "memory");
}
__device__ __forceinline__ void bulk_cp(uint32_t dst, const void* src, uint32_t bytes, uint32_t mbar) {
    asm volatile("cp.async.bulk.shared::cta.global.mbarrier::complete_tx::bytes [%0], [%1], %2, [%3];"
                 :: "r"(dst), "l"(src), "r"(bytes), "r"(mbar) : "memory");
}
__device__ __forceinline__ void ldm_x4(uint32_t* r, uint32_t addr) {
    asm volatile("ldmatrix.sync.aligned.m8n8.x4.shared.b16 {%0,%1,%2,%3}, [%4];"
                 : "=r"(r[0]), "=r"(r[1]), "=r"(r[2]), "=r"(r[3]) : "r"(addr));
}
__device__ __forceinline__ void mma_bf16(float* d, const uint32_t* a, uint32_t b0, uint32_t b1) {
    asm volatile("mma.sync.aligned.m16n8k16.row.col.f32.bf16.bf16.f32 "
                 "{%0,%1,%2,%3}, {%4,%5,%6,%7}, {%8,%9}, {%0,%1,%2,%3};"
                 : "+f"(d[0]), "+f"(d[1]), "+f"(d[2]), "+f"(d[3])
                 : "r"(a[0]), "r"(a[1]), "r"(a[2]), "r"(a[3]), "r"(b0), "r"(b1));
}

// ---------------------------------------------------------------------------
// Packed-tiled operand layout: rows grouped by 128 (tile), K by 32 (chunk).
// Tile (t, kc) = 16KB contiguous: 128 rows x 128B, row = [hi32|lo32] bf16
// groups, byte offset pre-swizzled with o ^ ((row&7)<<4).
// ---------------------------------------------------------------------------
__device__ __forceinline__ void packed_store(unsigned char* base, int NC, int r, int k,
                                             float v0, float v1) {
    size_t tb = (((size_t)(r >> 7) * NC + (k >> 5)) * 128 + (r & 127)) * 128;
    int j2 = (k & 31) * 2;
    int swz = (r & 7) << 4;
    __nv_bfloat16 h0 = __float2bfloat16(v0), h1 = __float2bfloat16(v1);
    float l0 = v0 - __bfloat162float(h0), l1 = v1 - __bfloat162float(h1);
    __nv_bfloat16 L0 = __float2bfloat16(l0), L1 = __float2bfloat16(l1);
    uint32_t hb = ((uint32_t)__bfloat16_as_ushort(h1) << 16) | __bfloat16_as_ushort(h0);
    uint32_t lb = ((uint32_t)__bfloat16_as_ushort(L1) << 16) | __bfloat16_as_ushort(L0);
    *(uint32_t*)(base + tb + (j2 ^ swz)) = hb;
    *(uint32_t*)(base + tb + ((j2 + 64) ^ swz)) = lb;
}

// ---------------------------------------------------------------------------
// transpose / sort / gather / pack
// ---------------------------------------------------------------------------
__global__ void transpose_k(const float* __restrict__ src, float* __restrict__ dst,
                            int R, int C) {
    __shared__ float tile[32][33];
    size_t bo = (size_t)blockIdx.z * R * C;
    int r0 = blockIdx.y * 32, c0 = blockIdx.x * 32;
    int tx = threadIdx.x, ty = threadIdx.y;
#pragma unroll
    for (int i = 0; i < 32; i += 8)
        tile[ty + i][tx] = src[bo + (size_t)(r0 + ty + i) * C + (c0 + tx)];
    __syncthreads();
#pragma unroll
    for (int i = 0; i < 32; i += 8)
        dst[bo + (size_t)(c0 + ty + i) * R + (r0 + tx)] = tile[tx][ty + i];
}

__global__ __launch_bounds__(512) void sort_k(const float* __restrict__ xm,
                                              float* __restrict__ xs,
                                              unsigned char* __restrict__ xsp,
                                              int* __restrict__ p) {
    __shared__ unsigned long long key[2048];
    __shared__ float val[2048];
    __shared__ int   rnk[2048];
    size_t base = (size_t)blockIdx.x * 2048;
    int tid = threadIdx.x;

    for (int i = tid; i < 2048; i += 512) {
        float v = xm[base + i];
        val[i] = v;
        unsigned u = __float_as_uint(v);
        u = (u & 0x80000000u) ? ~u : (u | 0x80000000u);
        key[i] = ((unsigned long long)u << 32) | (unsigned)i;
    }
    __syncthreads();

    for (int k2 = 2; k2 <= 2048; k2 <<= 1) {
        for (int j = k2 >> 1; j > 0; j >>= 1) {
            for (int i = tid; i < 2048; i += 512) {
                int l = i ^ j;
                if (l > i) {
                    unsigned long long a = key[i], b = key[l];
                    bool asc = ((i & k2) == 0);
                    if ((a > b) == asc) { key[i] = b; key[l] = a; }
                }
            }
            __syncthreads();
        }
    }

    for (int i = tid; i < 2048; i += 512) {
        int pi = (int)(unsigned)(key[i] & 0xffffffffu);
        p[base + i] = pi;
        rnk[pi] = i;
    }
    __syncthreads();
    int r = blockIdx.x;
    for (int i = 2 * tid; i < 2048; i += 1024) {
        float v0 = val[rnk[i]], v1 = val[rnk[i + 1]];
        xs[base + i] = v0;
        xs[base + i + 1] = v1;
        packed_store(xsp, 64, r, i, v0, v1);   // NC = 2048/32
    }
}

__global__ __launch_bounds__(512) void gather_k(const float* __restrict__ y,
                                                const int* __restrict__ p,
                                                float* __restrict__ zt) {
    size_t base = (size_t)blockIdx.x * 2048;
    for (int n = threadIdx.x; n < 2048; n += 512)
        zt[base + n] = y[base + p[base + n]];
}

__device__ __forceinline__ void pack_body(const float* __restrict__ in,
                                          unsigned char* __restrict__ out,
                                          int K, int bid, int tid) {
    size_t gid = (size_t)bid * 256 + tid;
    size_t r = gid / (unsigned)(K / 2);
    int k = (int)(gid - r * (unsigned)(K / 2)) * 2;
    const float* row = in + r * (size_t)K;
    packed_store(out, K / 32, (int)r, k, row[k], row[k + 1]);
}

__global__ __launch_bounds__(256) void pack_k(const float* __restrict__ in,
                                              unsigned char* __restrict__ out, int K) {
    pack_body(in, out, K, blockIdx.x, threadIdx.x);
}

// All four weight packs in ONE launch (keeps gemm1 at my launch index 3).
__global__ __launch_bounds__(256) void packW_k(const float* __restrict__ sw1, unsigned char* __restrict__ o1,
                                               const float* __restrict__ sw2, unsigned char* __restrict__ o2,
                                               const float* __restrict__ fw1, unsigned char* __restrict__ o3,
                                               const float* __restrict__ fw2, unsigned char* __restrict__ o4) {
    int b = blockIdx.x, t = threadIdx.x;
    if (b < 32768)       pack_body(sw1, o1, N_,  b,         t);
    else if (b < 65536)  pack_body(sw2, o2, HS_, b - 32768, t);
    else if (b < 73728)  pack_body(fw1, o3, F_,  b - 65536, t);
    else                 pack_body(fw2, o4, HF_, b - 73728, t);
}

// ---------------------------------------------------------------------------
// bf16x3 mma.sync GEMM. CTA tile 128x128, 256 thr, warp tile 32x64.
// 3-stage cp.async.bulk pipeline (32KB/stage), 2 CTAs/SM for overlap.
// MODE 0: bias+relu -> packed-tiled. MODE 1: bias+skip fp32. MODE 2: bias fp32.
// ---------------------------------------------------------------------------
#define S_ 3
#define STAGE_B 32768
#define GEMM_SMEM (1024 + S_ * STAGE_B)

template <int MODE>
__global__ __launch_bounds__(256, 2) void gemm_mma(
    const unsigned char* __restrict__ Ap, const unsigned char* __restrict__ Bp,
    const float* __restrict__ bias, const float* __restrict__ Skip,
    float* __restrict__ Cf, unsigned char* __restrict__ Cp,
    int M, int Ntot, int K) {
    extern __shared__ __align__(1024) unsigned char smem_raw[];
    const uint32_t sb = smem_u32(smem_raw);
    const int tid = threadIdx.x;
    const int lane = tid & 31, wid = tid >> 5;
    const int wm = wid & 3, wn = wid >> 2;         // 4 x 2 warp grid (M x N)
    const int NC = K / 32;
    const int m0 = blockIdx.y * 128, n0 = blockIdx.x * 128;

    const uint32_t FULL0 = sb;            // full[s] at sb+16s, free[s] at sb+16s+8
    const uint32_t DATA  = sb + 1024;

    if (tid == 0) {
        for (int s = 0; s < S_; s++) {
            mbar_init(FULL0 + 16 * s, 1);
            mbar_init(FULL0 + 16 * s + 8, 256);
        }
        asm volatile("fence.proxy.async.shared::cta;" ::: "memory");
    }
    __syncthreads();

    const unsigned char* Atile = Ap + (size_t)blockIdx.y * NC * 16384;
    const unsigned char* Btile = Bp + (size_t)blockIdx.x * NC * 16384;

    if (tid == 0) {
#pragma unroll
        for (int s = 0; s < S_ - 1; s++) {
            uint32_t st = DATA + (uint32_t)s * STAGE_B;
            mbar_expect_tx(FULL0 + 16 * s, STAGE_B);
            bulk_cp(st,          Atile + (size_t)s * 16384, 16384u, FULL0 + 16 * s);
            bulk_cp(st + 16384u, Btile + (size_t)s * 16384, 16384u, FULL0 + 16 * s);
        }
    }

    float acc[2][8][4];
#pragma unroll
    for (int a = 0; a < 2; a++)
#pragma unroll
        for (int b = 0; b < 8; b++)
#pragma unroll
            for (int c = 0; c < 4; c++) acc[a][b][c] = 0.f;

    const int lr = lane & 15;
    const int lh = (lane >> 4) << 4;

    for (int kc = 0; kc < NC; kc++) {
        const int s = kc % S_;
        if (tid == 0) {
            int kp = kc + S_ - 1;
            if (kp < NC) {
                int sp = kp % S_;
                if (kp >= S_) mbar_wait(FULL0 + 16 * sp + 8, ((kp / S_) - 1) & 1);
                uint32_t st = DATA + (uint32_t)sp * STAGE_B;
                mbar_expect_tx(FULL0 + 16 * sp, STAGE_B);
                bulk_cp(st,          Atile + (size_t)kp * 16384, 16384u, FULL0 + 16 * sp);
                bulk_cp(st + 16384u, Btile + (size_t)kp * 16384, 16384u, FULL0 + 16 * sp);
            }
        }
        mbar_wait(FULL0 + 16 * s, (kc / S_) & 1);

        const uint32_t Ab = DATA + (uint32_t)s * STAGE_B;
        const uint32_t Bb = Ab + 16384u;

        uint32_t a[2][2][4];   // [ks][mt] : Ah then overwritten by Al
        uint32_t bh[2][4][4];  // [ks][nq] : Bh cached across passes 1 & 3
#pragma unroll
        for (int ks = 0; ks < 2; ks++)
#pragma unroll
            for (int mt = 0; mt < 2; mt++) {
                int row = wm * 32 + mt * 16 + lr;
                ldm_x4(a[ks][mt], Ab + row * 128 + ((ks * 32 + lh) ^ ((row & 7) << 4)));
            }
#pragma unroll
        for (int ks = 0; ks < 2; ks++)
#pragma unroll
            for (int nq = 0; nq < 4; nq++) {
                int row = wn * 64 + nq * 16 + lr;
                ldm_x4(bh[ks][nq], Bb + row * 128 + ((ks * 32 + lh) ^ ((row & 7) << 4)));
            }
        // pass 1: Ah * Bh
#pragma unroll
        for (int ks = 0; ks < 2; ks++)
#pragma unroll
            for (int mt = 0; mt < 2; mt++)
#pragma unroll
                for (int nq = 0; nq < 4; nq++) {
                    mma_bf16(acc[mt][2 * nq],     a[ks][mt], bh[ks][nq][0], bh[ks][nq][2]);
                    mma_bf16(acc[mt][2 * nq + 1], a[ks][mt], bh[ks][nq][1], bh[ks][nq][3]);
                }
        // pass 2: Ah * Bl
#pragma unroll
        for (int ks = 0; ks < 2; ks++) {
            uint32_t bl[4][4];
#pragma unroll
            for (int nq = 0; nq < 4; nq++) {
                int row = wn * 64 + nq * 16 + lr;
                ldm_x4(bl[nq], Bb + row * 128 + ((64 + ks * 32 + lh) ^ ((row & 7) << 4)));
            }
#pragma unroll
            for (int mt = 0; mt < 2; mt++)
#pragma unroll
                for (int nq = 0; nq < 4; nq++) {
                    mma_bf16(acc[mt][2 * nq],     a[ks][mt], bl[nq][0], bl[nq][2]);
                    mma_bf16(acc[mt][2 * nq + 1], a[ks][mt], bl[nq][1], bl[nq][3]);
                }
        }
        // pass 3: Al * Bh
#pragma unroll
        for (int ks = 0; ks < 2; ks++)
#pragma unroll
            for (int mt = 0; mt < 2; mt++) {
                int row = wm * 32 + mt * 16 + lr;
                ldm_x4(a[ks][mt], Ab + row * 128 + ((64 + ks * 32 + lh) ^ ((row & 7) << 4)));
            }
#pragma unroll
        for (int ks = 0; ks < 2; ks++)
#pragma unroll
            for (int mt = 0; mt < 2; mt++)
#pragma unroll
                for (int nq = 0; nq < 4; nq++) {
                    mma_bf16(acc[mt][2 * nq],     a[ks][mt], bh[ks][nq][0], bh[ks][nq][2]);
                    mma_bf16(acc[mt][2 * nq + 1], a[ks][mt], bh[ks][nq][1], bh[ks][nq][3]);
                }
        mbar_arrive(FULL0 + 16 * s + 8);
    }

    // ---- epilogue ----
    const int NCo = Ntot / 32;
#pragma unroll
    for (int mt = 0; mt < 2; mt++) {
        int r0 = m0 + wm * 32 + mt * 16 + (lane >> 2);
#pragma unroll
        for (int nf = 0; nf < 8; nf++) {
            int c = n0 + wn * 64 + nf * 8 + (lane & 3) * 2;
            float b0 = bias[c], b1v = bias[c + 1];
            float v00 = acc[mt][nf][0] + b0, v01 = acc[mt][nf][1] + b1v;
            float v10 = acc[mt][nf][2] + b0, v11 = acc[mt][nf][3] + b1v;
            int r1 = r0 + 8;
            if (MODE == 0) {
                packed_store(Cp, NCo, r0, c, fmaxf(v00, 0.f), fmaxf(v01, 0.f));
                packed_store(Cp, NCo, r1, c, fmaxf(v10, 0.f), fmaxf(v11, 0.f));
            } else if (MODE == 1) {
                const float2 s0 = *(const float2*)(Skip + (size_t)r0 * Ntot + c);
                const float2 s1 = *(const float2*)(Skip + (size_t)r1 * Ntot + c);
                *(float2*)(Cf + (size_t)r0 * Ntot + c) = make_float2(v00 + s0.x, v01 + s0.y);
                *(float2*)(Cf + (size_t)r1 * Ntot + c) = make_float2(v10 + s1.x, v11 + s1.y);
            } else {
                *(float2*)(Cf + (size_t)r0 * Ntot + c) = make_float2(v00, v01);
                *(float2*)(Cf + (size_t)r1 * Ntot + c) = make_float2(v10, v11);
            }
        }
    }
}

// ---------------------------------------------------------------------------
extern "C" void kernel_launch(void* const* d_in, const int* in_sizes, int n_in,
                              void* d_out, int out_size) {
    const float* x   = (const float*)d_in[0];
    const float* sw1 = (const float*)d_in[1];
    const float* sb1 = (const float*)d_in[2];
    const float* sw2 = (const float*)d_in[3];
    const float* sb2 = (const float*)d_in[4];
    const float* fw1 = (const float*)d_in[5];
    const float* fb1 = (const float*)d_in[6];
    const float* fw2 = (const float*)d_in[7];
    const float* fb2 = (const float*)d_in[8];
    float* out = (float*)d_out;

    unsigned char *xm, *xs, *xsp, *p, *h, *w1, *w2, *w3, *w4;
    cudaGetSymbolAddress((void**)&xm,  g_xm);
    cudaGetSymbolAddress((void**)&xs,  g_xs);
    cudaGetSymbolAddress((void**)&xsp, g_xsp);
    cudaGetSymbolAddress((void**)&p,   g_p);
    cudaGetSymbolAddress((void**)&h,   g_h);
    cudaGetSymbolAddress((void**)&w1,  g_w1);
    cudaGetSymbolAddress((void**)&w2,  g_w2);
    cudaGetSymbolAddress((void**)&w3,  g_w3);
    cudaGetSymbolAddress((void**)&w4,  g_w4);

    cudaFuncSetAttribute((const void*)gemm_mma<0>, cudaFuncAttributeMaxDynamicSharedMemorySize, GEMM_SMEM);
    cudaFuncSetAttribute((const void*)gemm_mma<1>, cudaFuncAttributeMaxDynamicSharedMemorySize, GEMM_SMEM);
    cudaFuncSetAttribute((const void*)gemm_mma<2>, cudaFuncAttributeMaxDynamicSharedMemorySize, GEMM_SMEM);

    const int M1 = B_ * F_;   // 32768
    const int M2 = B_ * N_;   // 65536

    // launch order keeps gemm1 at my index 3 (ncu -s 5 lands there with 2 hidden launches)
    transpose_k<<<dim3(F_ / 32, N_ / 32, B_), dim3(32, 8)>>>(x, (float*)xm, N_, F_);    // 0
    sort_k<<<M1, 512>>>((const float*)xm, (float*)xs, xsp, (int*)p);                    // 1
    packW_k<<<81920, 256>>>(sw1, w1, sw2, w2, fw1, w3, fw2, w4);                        // 2

    // 3) h = relu(xs @ sw1^T + sb1) -> packed-tiled    <== ncu target
    gemm_mma<0><<<dim3(HS_ / 128, M1 / 128), 256, GEMM_SMEM>>>(                         // 3
        xsp, w1, sb1, nullptr, nullptr, h, M1, HS_, N_);

    // 4) y = h @ sw2^T + sb2 + xs -> fp32 (into xm)
    gemm_mma<1><<<dim3(N_ / 128, M1 / 128), 256, GEMM_SMEM>>>(
        h, w2, sb2, (const float*)xs, (float*)xm, nullptr, M1, N_, HS_);

    // 5) zt = gather(y, p) (into xsp as fp32)
    gather_k<<<M1, 512>>>((const float*)xm, (const int*)p, (float*)xsp);

    // 6) z[b,n,f] = zt[b,f,n] (into xs)
    transpose_k<<<dim3(N_ / 32, F_ / 32, B_), dim3(32, 8)>>>((const float*)xsp, (float*)xs, F_, N_);

    // 6b) pack z -> tiled (into xm)
    pack_k<<<(int)((size_t)M2 * F_ / 512), 256>>>((const float*)xs, xm, F_);

    // 7) h2 = relu(z @ fw1^T + fb1) -> packed-tiled (into h)
    gemm_mma<0><<<dim3(HF_ / 128, M2 / 128), 256, GEMM_SMEM>>>(
        xm, w3, fb1, nullptr, nullptr, h, M2, HF_, F_);

    // 8) out = h2 @ fw2^T + fb2 -> fp32
    gemm_mma<2><<<dim3(OUT_ / 128, M2 / 128), 256, GEMM_SMEM>>>(
        h, w4, fb2, nullptr, out, nullptr, M2, OUT_, HF_);
}